// round 9
// baseline (speedup 1.0000x reference)
#include <cuda_runtime.h>
#include <math.h>

// RoI Align pyramid (FPN) — cp.async pipelined version.
//   d_in[0] metadata [1,3] f32, d_in[1] boxes [1,1024,4] f32
//   d_in[2..5] p2..p5: [1,H,H,256] f32, H = 256,128,64,32
// Output: [1,1024,7,7,256] f32
//
// One block per box, 256 threads. Samples processed in pairs through a
// 3-deep smem ring. Load phase: thread = (corner 0..3, float4 chunk 0..63),
// 2x LDGSTS.128 per pair -> MLP independent of register file. Compute
// phase: thread = (sample-of-pair, float2 chunk 0..127), 4x LDS.64 +
// bilinear FMA + STG.64 streaming store.

#define EXTENT   7
#define NSAMP    49          // 7*7
#define NPAIRS   25          // ceil(49/2)
#define DEPTH    3           // pair-stages in flight
#define NBOX     1024
#define CH4      64u         // 256 channels / 4 (float4 chunks)
#define CH2      128u        // 256 channels / 2 (float2 chunks)

__device__ __forceinline__ void cp_async16(void* smem_dst, const void* gsrc) {
    unsigned saddr = (unsigned)__cvta_generic_to_shared(smem_dst);
    asm volatile("cp.async.cg.shared.global [%0], [%1], 16;"
                 :: "r"(saddr), "l"(gsrc));
}
__device__ __forceinline__ void cp_async_commit() {
    asm volatile("cp.async.commit_group;");
}
__device__ __forceinline__ void cp_async_wait2() {
    asm volatile("cp.async.wait_group 2;");
}

__global__ __launch_bounds__(256, 4)
void roi_align_pyramid_kernel(const float* __restrict__ metadata,
                              const float* __restrict__ boxes,
                              const float* __restrict__ p2,
                              const float* __restrict__ p3,
                              const float* __restrict__ p4,
                              const float* __restrict__ p5,
                              float* __restrict__ out)
{
    // ring: [stage][sampleInPair][corner][chunk]
    __shared__ float4 buf[DEPTH][2][4][CH4];

    const int box = blockIdx.x;

    const float rows = metadata[0];
    const float cols = metadata[1];

    const float x1 = boxes[box * 4 + 0];
    const float y1 = boxes[box * 4 + 1];
    const float x2 = boxes[box * 4 + 2];
    const float y2 = boxes[box * 4 + 3];

    const float h = y2 - y1;
    const float w = x2 - x1;

    // roi_level = clip(4 + round(log2(sqrt(h*w)/sqrt(rows*cols))), 2, 5)
    float rl = logf(sqrtf(h * w) / sqrtf(rows * cols)) * (1.0f / logf(2.0f));
    rl = fminf(5.0f, fmaxf(2.0f, 4.0f + rintf(rl)));
    const int lvl = (int)rl;  // 2..5

    const float* feat;
    int H;
    switch (lvl) {
        case 2: feat = p2; H = 256; break;
        case 3: feat = p3; H = 128; break;
        case 4: feat = p4; H = 64;  break;
        default: feat = p5; H = 32; break;
    }
    const int W = H;

    const float inv_r = 1.0f / (rows - 1.0f);
    const float inv_c = 1.0f / (cols - 1.0f);
    const float ny1 = y1 * inv_r;
    const float ny2 = y2 * inv_r;
    const float nx1 = x1 * inv_c;
    const float nx2 = x2 * inv_c;
    const float dny = ny2 - ny1;
    const float dnx = nx2 - nx1;
    const float Hm1 = (float)(H - 1);
    const float Wm1 = (float)(W - 1);
    const unsigned rowstep = (unsigned)W * CH4;   // float4 units

    const unsigned t = threadIdx.x;
    // load role
    const unsigned ld_chunk  = t & 63u;
    const unsigned ld_corner = (t >> 6) & 3u;
    const unsigned cornOff   = (ld_corner & 1u) * CH4 + (ld_corner >> 1) * rowstep;
    // compute role
    const unsigned cp_samp = t >> 7;      // 0..1
    const unsigned cp_pos  = t & 127u;    // float2 chunk

    const float4* __restrict__ f4 = (const float4*)feat;
    float2* __restrict__ o2 = (float2*)out + (unsigned)box * (NSAMP * CH2);

    // sample s -> grid coords
    auto sample_coords = [&](int s, float& ys, float& xs) {
        const int gy = s / EXTENT;
        const int gx = s - gy * EXTENT;
        const float gyf = (float)gy * (1.0f / (float)(EXTENT - 1));
        const float gxf = (float)gx * (1.0f / (float)(EXTENT - 1));
        ys = (ny1 + dny * gyf) * Hm1;
        xs = (nx1 + dnx * gxf) * Wm1;
    };

    auto base_of = [&](int s) -> unsigned {
        float ys, xs;
        sample_coords(s, ys, xs);
        const float y0f = fminf(fmaxf(floorf(ys), 0.0f), (float)(H - 2));
        const float x0f = fminf(fmaxf(floorf(xs), 0.0f), (float)(W - 2));
        return ((unsigned)((int)y0f * W + (int)x0f)) * CH4;
    };

    auto weights_of = [&](int s, float& w00, float& w01, float& w10, float& w11) {
        float ys, xs;
        sample_coords(s, ys, xs);
        const float y0f = fminf(fmaxf(floorf(ys), 0.0f), (float)(H - 2));
        const float x0f = fminf(fmaxf(floorf(xs), 0.0f), (float)(W - 2));
        const float wy = ys - y0f;
        const float wx = xs - x0f;
        w00 = (1.0f - wy) * (1.0f - wx);
        w01 = (1.0f - wy) * wx;
        w10 = wy * (1.0f - wx);
        w11 = wy * wx;
    };

    // issue loads for pair p (always commits a group, possibly empty)
    auto issue_pair = [&](int p) {
        if (p < NPAIRS) {
            const int slot = p % DEPTH;
            #pragma unroll
            for (int samp = 0; samp < 2; samp++) {
                const int s = 2 * p + samp;
                if (s < NSAMP) {
                    const unsigned base = base_of(s);
                    cp_async16(&buf[slot][samp][ld_corner][ld_chunk],
                               &f4[base + cornOff + ld_chunk]);
                }
            }
        }
        cp_async_commit();
    };

    // prologue: fill the ring
    issue_pair(0);
    issue_pair(1);
    issue_pair(2);

    for (int p = 0; p < NPAIRS; p++) {
        cp_async_wait2();       // oldest stage (p) landed
        __syncthreads();

        const int s = 2 * p + (int)cp_samp;
        float2 r;
        bool valid = (s < NSAMP);
        if (valid) {
            float w00, w01, w10, w11;
            weights_of(s, w00, w01, w10, w11);
            const int slot = p % DEPTH;
            const float2 f00 = ((const float2*)buf[slot][cp_samp][0])[cp_pos];
            const float2 f01 = ((const float2*)buf[slot][cp_samp][1])[cp_pos];
            const float2 f10 = ((const float2*)buf[slot][cp_samp][2])[cp_pos];
            const float2 f11 = ((const float2*)buf[slot][cp_samp][3])[cp_pos];
            r.x = f00.x * w00 + f01.x * w01 + f10.x * w10 + f11.x * w11;
            r.y = f00.y * w00 + f01.y * w01 + f10.y * w10 + f11.y * w11;
        }
        __syncthreads();        // all reads of slot done before refill
        issue_pair(p + DEPTH);
        if (valid) {
            __stcs(&o2[(unsigned)s * CH2 + cp_pos], r);
        }
    }
}

extern "C" void kernel_launch(void* const* d_in, const int* in_sizes, int n_in,
                              void* d_out, int out_size)
{
    const float* metadata = (const float*)d_in[0];
    const float* boxes    = (const float*)d_in[1];
    const float* p2       = (const float*)d_in[2];
    const float* p3       = (const float*)d_in[3];
    const float* p4       = (const float*)d_in[4];
    const float* p5       = (const float*)d_in[5];
    float* out = (float*)d_out;

    roi_align_pyramid_kernel<<<NBOX, 256>>>(metadata, boxes, p2, p3, p4, p5, out);
}

// round 10
// speedup vs baseline: 1.0743x; 1.0743x over previous
#include <cuda_runtime.h>
#include <math.h>

// RoI Align pyramid (FPN).
//   d_in[0] metadata [1,3] f32, d_in[1] boxes [1,1024,4] f32
//   d_in[2..5] p2..p5: [1,H,H,256] f32, H = 256,128,64,32
// Output: [1,1024,7,7,256] f32
//
// One block per box, 256 threads in 4 groups of 64 lanes; lane = one
// float4 channel chunk. Loop unrolled x3 -> 12 independent 128-bit
// loads in flight per thread (launch_bounds(256,3), ~80 regs).
// Output stores streaming (__stcs). Plain __ldg feature loads (L2
// evict_last was tested and is neutral; cp.async pipeline regressed).

#define EXTENT 7
#define NSAMP  49
#define NBOX   1024
#define CH4    64u   // 256 channels / 4

__global__ __launch_bounds__(256, 3)
void roi_align_pyramid_kernel(const float* __restrict__ metadata,
                              const float* __restrict__ boxes,
                              const float* __restrict__ p2,
                              const float* __restrict__ p3,
                              const float* __restrict__ p4,
                              const float* __restrict__ p5,
                              float* __restrict__ out)
{
    const int box = blockIdx.x;

    const float rows = metadata[0];
    const float cols = metadata[1];

    const float x1 = boxes[box * 4 + 0];
    const float y1 = boxes[box * 4 + 1];
    const float x2 = boxes[box * 4 + 2];
    const float y2 = boxes[box * 4 + 3];

    const float h = y2 - y1;
    const float w = x2 - x1;

    // roi_level = clip(4 + round(log2(sqrt(h*w)/sqrt(rows*cols))), 2, 5)
    float rl = logf(sqrtf(h * w) / sqrtf(rows * cols)) * (1.0f / logf(2.0f));
    rl = fminf(5.0f, fmaxf(2.0f, 4.0f + rintf(rl)));
    const int lvl = (int)rl;  // 2..5

    const float* feat;
    int H;
    switch (lvl) {
        case 2: feat = p2; H = 256; break;
        case 3: feat = p3; H = 128; break;
        case 4: feat = p4; H = 64;  break;
        default: feat = p5; H = 32; break;
    }
    const int W = H;

    const float inv_r = 1.0f / (rows - 1.0f);
    const float inv_c = 1.0f / (cols - 1.0f);
    const float ny1 = y1 * inv_r;
    const float ny2 = y2 * inv_r;
    const float nx1 = x1 * inv_c;
    const float nx2 = x2 * inv_c;
    const float dny = ny2 - ny1;
    const float dnx = nx2 - nx1;
    const float Hm1 = (float)(H - 1);
    const float Wm1 = (float)(W - 1);

    const unsigned t      = threadIdx.x;
    const unsigned lane_c = t & (CH4 - 1u);  // float4 channel index 0..63
    const unsigned sgrp   = t >> 6;          // sample group 0..3
    const unsigned rowstep = (unsigned)W * CH4;

    const float4* __restrict__ f4 = (const float4*)feat;
    float4* __restrict__ o4 = (float4*)out + (unsigned)box * (NSAMP * CH4);

    // Per-sample addressing: sample index s in [0,49)
    auto sample_setup = [&](int s, unsigned& b00,
                            float& w00, float& w01, float& w10, float& w11) {
        const int gy = s / EXTENT;
        const int gx = s - gy * EXTENT;

        const float gyf = (float)gy * (1.0f / (float)(EXTENT - 1));
        const float gxf = (float)gx * (1.0f / (float)(EXTENT - 1));

        const float ys = (ny1 + dny * gyf) * Hm1;
        const float xs = (nx1 + dnx * gxf) * Wm1;

        const float y0f = fminf(fmaxf(floorf(ys), 0.0f), (float)(H - 2));
        const float x0f = fminf(fmaxf(floorf(xs), 0.0f), (float)(W - 2));
        const float wy = ys - y0f;
        const float wx = xs - x0f;

        w00 = (1.0f - wy) * (1.0f - wx);
        w01 = (1.0f - wy) * wx;
        w10 = wy * (1.0f - wx);
        w11 = wy * wx;

        b00 = ((unsigned)((int)y0f * W + (int)x0f)) * CH4 + lane_c;
    };

    int s = (int)sgrp;
    // Unrolled x3: 12 independent LDG.128 in flight per thread
    for (; s + 8 < NSAMP; s += 12) {
        unsigned a_b00; float a00, a01, a10, a11;
        unsigned b_b00; float b00w, b01w, b10w, b11w;
        unsigned c_b00; float c00, c01, c10, c11;
        sample_setup(s,     a_b00, a00, a01, a10, a11);
        sample_setup(s + 4, b_b00, b00w, b01w, b10w, b11w);
        sample_setup(s + 8, c_b00, c00, c01, c10, c11);

        const float4 fa00 = __ldg(&f4[a_b00]);
        const float4 fa01 = __ldg(&f4[a_b00 + CH4]);
        const float4 fa10 = __ldg(&f4[a_b00 + rowstep]);
        const float4 fa11 = __ldg(&f4[a_b00 + rowstep + CH4]);
        const float4 fb00 = __ldg(&f4[b_b00]);
        const float4 fb01 = __ldg(&f4[b_b00 + CH4]);
        const float4 fb10 = __ldg(&f4[b_b00 + rowstep]);
        const float4 fb11 = __ldg(&f4[b_b00 + rowstep + CH4]);
        const float4 fc00 = __ldg(&f4[c_b00]);
        const float4 fc01 = __ldg(&f4[c_b00 + CH4]);
        const float4 fc10 = __ldg(&f4[c_b00 + rowstep]);
        const float4 fc11 = __ldg(&f4[c_b00 + rowstep + CH4]);

        float4 ra;
        ra.x = fa00.x * a00 + fa01.x * a01 + fa10.x * a10 + fa11.x * a11;
        ra.y = fa00.y * a00 + fa01.y * a01 + fa10.y * a10 + fa11.y * a11;
        ra.z = fa00.z * a00 + fa01.z * a01 + fa10.z * a10 + fa11.z * a11;
        ra.w = fa00.w * a00 + fa01.w * a01 + fa10.w * a10 + fa11.w * a11;
        __stcs(&o4[(unsigned)s * CH4 + lane_c], ra);

        float4 rb;
        rb.x = fb00.x * b00w + fb01.x * b01w + fb10.x * b10w + fb11.x * b11w;
        rb.y = fb00.y * b00w + fb01.y * b01w + fb10.y * b10w + fb11.y * b11w;
        rb.z = fb00.z * b00w + fb01.z * b01w + fb10.z * b10w + fb11.z * b11w;
        rb.w = fb00.w * b00w + fb01.w * b01w + fb10.w * b10w + fb11.w * b11w;
        __stcs(&o4[(unsigned)(s + 4) * CH4 + lane_c], rb);

        float4 rc;
        rc.x = fc00.x * c00 + fc01.x * c01 + fc10.x * c10 + fc11.x * c11;
        rc.y = fc00.y * c00 + fc01.y * c01 + fc10.y * c10 + fc11.y * c11;
        rc.z = fc00.z * c00 + fc01.z * c01 + fc10.z * c10 + fc11.z * c11;
        rc.w = fc00.w * c00 + fc01.w * c01 + fc10.w * c10 + fc11.w * c11;
        __stcs(&o4[(unsigned)(s + 8) * CH4 + lane_c], rc);
    }
    // Tail (only group 0 reaches s=48)
    if (s < NSAMP) {
        unsigned b00i; float w00, w01, w10, w11;
        sample_setup(s, b00i, w00, w01, w10, w11);
        const float4 f00 = __ldg(&f4[b00i]);
        const float4 f01 = __ldg(&f4[b00i + CH4]);
        const float4 f10 = __ldg(&f4[b00i + rowstep]);
        const float4 f11 = __ldg(&f4[b00i + rowstep + CH4]);
        float4 r;
        r.x = f00.x * w00 + f01.x * w01 + f10.x * w10 + f11.x * w11;
        r.y = f00.y * w00 + f01.y * w01 + f10.y * w10 + f11.y * w11;
        r.z = f00.z * w00 + f01.z * w01 + f10.z * w10 + f11.z * w11;
        r.w = f00.w * w00 + f01.w * w01 + f10.w * w10 + f11.w * w11;
        __stcs(&o4[(unsigned)s * CH4 + lane_c], r);
    }
}

extern "C" void kernel_launch(void* const* d_in, const int* in_sizes, int n_in,
                              void* d_out, int out_size)
{
    const float* metadata = (const float*)d_in[0];
    const float* boxes    = (const float*)d_in[1];
    const float* p2       = (const float*)d_in[2];
    const float* p3       = (const float*)d_in[3];
    const float* p4       = (const float*)d_in[4];
    const float* p5       = (const float*)d_in[5];
    float* out = (float*)d_out;

    roi_align_pyramid_kernel<<<NBOX, 256>>>(metadata, boxes, p2, p3, p4, p5, out);
}

// round 11
// speedup vs baseline: 1.1517x; 1.0721x over previous
#include <cuda_runtime.h>
#include <math.h>

// RoI Align pyramid (FPN).
//   d_in[0] metadata [1,3] f32, d_in[1] boxes [1,1024,4] f32
//   d_in[2..5] p2..p5: [1,H,H,256] f32, H = 256,128,64,32
// Output: [1,1024,7,7,256] f32
//
// One block per box, 128 threads = 2 sample-groups of 64 lanes; lane =
// one float4 channel chunk. Unroll x2 -> 8 independent LDG.128 in
// flight per thread. launch_bounds(128,8): 8 CTAs/SM, 1024 blocks in a
// SINGLE wave (1024 < 148*8), eliminating the 1.7-wave tail of the
// 256-thread config. Streaming output stores (__stcs).

#define EXTENT 7
#define NSAMP  49
#define NBOX   1024
#define CH4    64u   // 256 channels / 4

__global__ __launch_bounds__(128, 8)
void roi_align_pyramid_kernel(const float* __restrict__ metadata,
                              const float* __restrict__ boxes,
                              const float* __restrict__ p2,
                              const float* __restrict__ p3,
                              const float* __restrict__ p4,
                              const float* __restrict__ p5,
                              float* __restrict__ out)
{
    const int box = blockIdx.x;

    const float rows = metadata[0];
    const float cols = metadata[1];

    const float x1 = boxes[box * 4 + 0];
    const float y1 = boxes[box * 4 + 1];
    const float x2 = boxes[box * 4 + 2];
    const float y2 = boxes[box * 4 + 3];

    const float h = y2 - y1;
    const float w = x2 - x1;

    // roi_level = clip(4 + round(log2(sqrt(h*w)/sqrt(rows*cols))), 2, 5)
    float rl = logf(sqrtf(h * w) / sqrtf(rows * cols)) * (1.0f / logf(2.0f));
    rl = fminf(5.0f, fmaxf(2.0f, 4.0f + rintf(rl)));
    const int lvl = (int)rl;  // 2..5

    const float* feat;
    int H;
    switch (lvl) {
        case 2: feat = p2; H = 256; break;
        case 3: feat = p3; H = 128; break;
        case 4: feat = p4; H = 64;  break;
        default: feat = p5; H = 32; break;
    }
    const int W = H;

    const float inv_r = 1.0f / (rows - 1.0f);
    const float inv_c = 1.0f / (cols - 1.0f);
    const float ny1 = y1 * inv_r;
    const float ny2 = y2 * inv_r;
    const float nx1 = x1 * inv_c;
    const float nx2 = x2 * inv_c;
    const float dny = ny2 - ny1;
    const float dnx = nx2 - nx1;
    const float Hm1 = (float)(H - 1);
    const float Wm1 = (float)(W - 1);

    const unsigned t      = threadIdx.x;
    const unsigned lane_c = t & (CH4 - 1u);  // float4 channel index 0..63
    const unsigned sgrp   = t >> 6;          // sample group 0..1
    const unsigned rowstep = (unsigned)W * CH4;

    const float4* __restrict__ f4 = (const float4*)feat;
    float4* __restrict__ o4 = (float4*)out + (unsigned)box * (NSAMP * CH4);

    // Per-sample addressing: sample index s in [0,49)
    auto sample_setup = [&](int s, unsigned& b00,
                            float& w00, float& w01, float& w10, float& w11) {
        const int gy = s / EXTENT;
        const int gx = s - gy * EXTENT;

        const float gyf = (float)gy * (1.0f / (float)(EXTENT - 1));
        const float gxf = (float)gx * (1.0f / (float)(EXTENT - 1));

        const float ys = (ny1 + dny * gyf) * Hm1;
        const float xs = (nx1 + dnx * gxf) * Wm1;

        const float y0f = fminf(fmaxf(floorf(ys), 0.0f), (float)(H - 2));
        const float x0f = fminf(fmaxf(floorf(xs), 0.0f), (float)(W - 2));
        const float wy = ys - y0f;
        const float wx = xs - x0f;

        w00 = (1.0f - wy) * (1.0f - wx);
        w01 = (1.0f - wy) * wx;
        w10 = wy * (1.0f - wx);
        w11 = wy * wx;

        b00 = ((unsigned)((int)y0f * W + (int)x0f)) * CH4 + lane_c;
    };

    // Group g handles samples g, g+2, g+4, ...; unroll x2 (s, s+2), step 4.
    int s = (int)sgrp;
    for (; s + 2 < NSAMP; s += 4) {
        unsigned a_b00; float a00, a01, a10, a11;
        unsigned b_b00; float b00w, b01w, b10w, b11w;
        sample_setup(s,     a_b00, a00, a01, a10, a11);
        sample_setup(s + 2, b_b00, b00w, b01w, b10w, b11w);

        const float4 fa00 = __ldg(&f4[a_b00]);
        const float4 fa01 = __ldg(&f4[a_b00 + CH4]);
        const float4 fa10 = __ldg(&f4[a_b00 + rowstep]);
        const float4 fa11 = __ldg(&f4[a_b00 + rowstep + CH4]);
        const float4 fb00 = __ldg(&f4[b_b00]);
        const float4 fb01 = __ldg(&f4[b_b00 + CH4]);
        const float4 fb10 = __ldg(&f4[b_b00 + rowstep]);
        const float4 fb11 = __ldg(&f4[b_b00 + rowstep + CH4]);

        float4 ra;
        ra.x = fa00.x * a00 + fa01.x * a01 + fa10.x * a10 + fa11.x * a11;
        ra.y = fa00.y * a00 + fa01.y * a01 + fa10.y * a10 + fa11.y * a11;
        ra.z = fa00.z * a00 + fa01.z * a01 + fa10.z * a10 + fa11.z * a11;
        ra.w = fa00.w * a00 + fa01.w * a01 + fa10.w * a10 + fa11.w * a11;
        __stcs(&o4[(unsigned)s * CH4 + lane_c], ra);

        float4 rb;
        rb.x = fb00.x * b00w + fb01.x * b01w + fb10.x * b10w + fb11.x * b11w;
        rb.y = fb00.y * b00w + fb01.y * b01w + fb10.y * b10w + fb11.y * b11w;
        rb.z = fb00.z * b00w + fb01.z * b01w + fb10.z * b10w + fb11.z * b11w;
        rb.w = fb00.w * b00w + fb01.w * b01w + fb10.w * b10w + fb11.w * b11w;
        __stcs(&o4[(unsigned)(s + 2) * CH4 + lane_c], rb);
    }
    // Tail: group 0 reaches s=48
    if (s < NSAMP) {
        unsigned b00i; float w00, w01, w10, w11;
        sample_setup(s, b00i, w00, w01, w10, w11);
        const float4 f00 = __ldg(&f4[b00i]);
        const float4 f01 = __ldg(&f4[b00i + CH4]);
        const float4 f10 = __ldg(&f4[b00i + rowstep]);
        const float4 f11 = __ldg(&f4[b00i + rowstep + CH4]);
        float4 r;
        r.x = f00.x * w00 + f01.x * w01 + f10.x * w10 + f11.x * w11;
        r.y = f00.y * w00 + f01.y * w01 + f10.y * w10 + f11.y * w11;
        r.z = f00.z * w00 + f01.z * w01 + f10.z * w10 + f11.z * w11;
        r.w = f00.w * w00 + f01.w * w01 + f10.w * w10 + f11.w * w11;
        __stcs(&o4[(unsigned)s * CH4 + lane_c], r);
    }
}

extern "C" void kernel_launch(void* const* d_in, const int* in_sizes, int n_in,
                              void* d_out, int out_size)
{
    const float* metadata = (const float*)d_in[0];
    const float* boxes    = (const float*)d_in[1];
    const float* p2       = (const float*)d_in[2];
    const float* p3       = (const float*)d_in[3];
    const float* p4       = (const float*)d_in[4];
    const float* p5       = (const float*)d_in[5];
    float* out = (float*)d_out;

    roi_align_pyramid_kernel<<<NBOX, 128>>>(metadata, boxes, p2, p3, p4, p5, out);
}

// round 12
// speedup vs baseline: 1.2653x; 1.0986x over previous
#include <cuda_runtime.h>
#include <math.h>

// RoI Align pyramid (FPN) — per-warp cp.async pipeline, no block barriers.
//   d_in[0] metadata [1,3] f32, d_in[1] boxes [1,1024,4] f32
//   d_in[2..5] p2..p5: [1,H,H,256] f32, H = 256,128,64,32
// Output: [1,1024,7,7,256] f32
//
// One block per box, 64 threads = 2 warps. Warp w handles samples
// s = w, w+2, ... through a private 3-deep smem ring (4KB/stage:
// 4 corners x 64 float4). Lane l stages chunks l and l+32 of every
// corner with cp.async (8x LDGSTS.128 per stage) and later consumes
// EXACTLY the bytes it staged -> cp.async.wait_group is sufficient
// ordering; no __syncwarp/__syncthreads anywhere in the pipeline.
// In-flight bytes decoupled from the register file. 9 CTAs/SM
// (24KB smem), single wave. Streaming output stores.

#define EXTENT 7
#define NSAMP  49
#define NBOX   1024
#define CH4    64u   // 256 channels / 4
#define DEPTH  3

__device__ __forceinline__ void cp_async16(void* smem_dst, const void* gsrc) {
    unsigned saddr = (unsigned)__cvta_generic_to_shared(smem_dst);
    asm volatile("cp.async.cg.shared.global [%0], [%1], 16;"
                 :: "r"(saddr), "l"(gsrc));
}
__device__ __forceinline__ void cp_async_commit() {
    asm volatile("cp.async.commit_group;");
}
__device__ __forceinline__ void cp_async_wait_upto2() {
    asm volatile("cp.async.wait_group 2;");   // DEPTH-1
}

__global__ __launch_bounds__(64, 9)
void roi_align_pyramid_kernel(const float* __restrict__ metadata,
                              const float* __restrict__ boxes,
                              const float* __restrict__ p2,
                              const float* __restrict__ p3,
                              const float* __restrict__ p4,
                              const float* __restrict__ p5,
                              float* __restrict__ out)
{
    // [warp][stage][corner][chunk]  = 2*3*4*64*16B = 24KB
    __shared__ float4 buf[2][DEPTH][4][CH4];

    const int box = blockIdx.x;

    const float rows = metadata[0];
    const float cols = metadata[1];

    const float x1 = boxes[box * 4 + 0];
    const float y1 = boxes[box * 4 + 1];
    const float x2 = boxes[box * 4 + 2];
    const float y2 = boxes[box * 4 + 3];

    const float h = y2 - y1;
    const float w = x2 - x1;

    // roi_level = clip(4 + round(log2(sqrt(h*w)/sqrt(rows*cols))), 2, 5)
    float rl = logf(sqrtf(h * w) / sqrtf(rows * cols)) * (1.0f / logf(2.0f));
    rl = fminf(5.0f, fmaxf(2.0f, 4.0f + rintf(rl)));
    const int lvl = (int)rl;  // 2..5

    const float* feat;
    int H;
    switch (lvl) {
        case 2: feat = p2; H = 256; break;
        case 3: feat = p3; H = 128; break;
        case 4: feat = p4; H = 64;  break;
        default: feat = p5; H = 32; break;
    }
    const int W = H;

    const float inv_r = 1.0f / (rows - 1.0f);
    const float inv_c = 1.0f / (cols - 1.0f);
    const float ny1 = y1 * inv_r;
    const float ny2 = y2 * inv_r;
    const float nx1 = x1 * inv_c;
    const float nx2 = x2 * inv_c;
    const float dny = ny2 - ny1;
    const float dnx = nx2 - nx1;
    const float Hm1 = (float)(H - 1);
    const float Wm1 = (float)(W - 1);
    const unsigned rowstep = (unsigned)W * CH4;  // float4 units

    const unsigned t  = threadIdx.x;
    const unsigned wp = t >> 5;   // warp 0..1
    const unsigned l  = t & 31u;  // lane

    const float4* __restrict__ f4 = (const float4*)feat;
    float4* __restrict__ o4 = (float4*)out + (unsigned)box * (NSAMP * CH4);

    // warp wp owns samples s = wp + 2*i
    const int nsw = (wp == 0) ? 25 : 24;

    auto sample_coords = [&](int s, float& ys, float& xs) {
        const int gy = s / EXTENT;
        const int gx = s - gy * EXTENT;
        const float gyf = (float)gy * (1.0f / (float)(EXTENT - 1));
        const float gxf = (float)gx * (1.0f / (float)(EXTENT - 1));
        ys = (ny1 + dny * gyf) * Hm1;
        xs = (nx1 + dnx * gxf) * Wm1;
    };

    // stage loads for owned-sample index i (always commits, maybe empty)
    auto issue = [&](int i) {
        if (i < nsw) {
            const int s = (int)wp + 2 * i;
            float ys, xs;
            sample_coords(s, ys, xs);
            const float y0f = fminf(fmaxf(floorf(ys), 0.0f), (float)(H - 2));
            const float x0f = fminf(fmaxf(floorf(xs), 0.0f), (float)(W - 2));
            const unsigned base = ((unsigned)((int)y0f * W + (int)x0f)) * CH4;
            const int st = i % DEPTH;
            const unsigned c0 = base + l;
            const unsigned c1 = base + CH4 + l;
            const unsigned c2 = base + rowstep + l;
            const unsigned c3 = base + rowstep + CH4 + l;
            cp_async16(&buf[wp][st][0][l],       &f4[c0]);
            cp_async16(&buf[wp][st][0][l + 32],  &f4[c0 + 32]);
            cp_async16(&buf[wp][st][1][l],       &f4[c1]);
            cp_async16(&buf[wp][st][1][l + 32],  &f4[c1 + 32]);
            cp_async16(&buf[wp][st][2][l],       &f4[c2]);
            cp_async16(&buf[wp][st][2][l + 32],  &f4[c2 + 32]);
            cp_async16(&buf[wp][st][3][l],       &f4[c3]);
            cp_async16(&buf[wp][st][3][l + 32],  &f4[c3 + 32]);
        }
        cp_async_commit();
    };

    issue(0);
    issue(1);
    issue(2);

    for (int i = 0; i < nsw; i++) {
        const int s  = (int)wp + 2 * i;
        const int st = i % DEPTH;

        float ys, xs;
        sample_coords(s, ys, xs);
        const float y0f = fminf(fmaxf(floorf(ys), 0.0f), (float)(H - 2));
        const float x0f = fminf(fmaxf(floorf(xs), 0.0f), (float)(W - 2));
        const float wy = ys - y0f;
        const float wx = xs - x0f;
        const float w00 = (1.0f - wy) * (1.0f - wx);
        const float w01 = (1.0f - wy) * wx;
        const float w10 = wy * (1.0f - wx);
        const float w11 = wy * wx;

        cp_async_wait_upto2();   // stage i landed (this lane's own loads)

        const float4 a00 = buf[wp][st][0][l];
        const float4 a01 = buf[wp][st][1][l];
        const float4 a10 = buf[wp][st][2][l];
        const float4 a11 = buf[wp][st][3][l];
        float4 ra;
        ra.x = a00.x * w00 + a01.x * w01 + a10.x * w10 + a11.x * w11;
        ra.y = a00.y * w00 + a01.y * w01 + a10.y * w10 + a11.y * w11;
        ra.z = a00.z * w00 + a01.z * w01 + a10.z * w10 + a11.z * w11;
        ra.w = a00.w * w00 + a01.w * w01 + a10.w * w10 + a11.w * w11;
        __stcs(&o4[(unsigned)s * CH4 + l], ra);

        const float4 b00 = buf[wp][st][0][l + 32];
        const float4 b01 = buf[wp][st][1][l + 32];
        const float4 b10 = buf[wp][st][2][l + 32];
        const float4 b11 = buf[wp][st][3][l + 32];
        float4 rb;
        rb.x = b00.x * w00 + b01.x * w01 + b10.x * w10 + b11.x * w11;
        rb.y = b00.y * w00 + b01.y * w01 + b10.y * w10 + b11.y * w11;
        rb.z = b00.z * w00 + b01.z * w01 + b10.z * w10 + b11.z * w11;
        rb.w = b00.w * w00 + b01.w * w01 + b10.w * w10 + b11.w * w11;
        __stcs(&o4[(unsigned)s * CH4 + l + 32], rb);

        issue(i + DEPTH);        // refill the slot just drained
    }
}

extern "C" void kernel_launch(void* const* d_in, const int* in_sizes, int n_in,
                              void* d_out, int out_size)
{
    const float* metadata = (const float*)d_in[0];
    const float* boxes    = (const float*)d_in[1];
    const float* p2       = (const float*)d_in[2];
    const float* p3       = (const float*)d_in[3];
    const float* p4       = (const float*)d_in[4];
    const float* p5       = (const float*)d_in[5];
    float* out = (float*)d_out;

    roi_align_pyramid_kernel<<<NBOX, 64>>>(metadata, boxes, p2, p3, p4, p5, out);
}